// round 7
// baseline (speedup 1.0000x reference)
#include <cuda_runtime.h>
#include <cuda_fp16.h>
#include <cstdint>

namespace {

constexpr int NH  = 32;    // query heads
constexpr int HS  = 128;   // head size
constexpr int KVH = 8;     // kv heads
constexpr int Bb  = 2;
constexpr int Ss  = 2048;

constexpr int BR = 64;     // query rows per CTA
constexpr int BC = 64;     // keys per tile
constexpr int NTILES_TOT = Ss / BC;                 // 32
constexpr int TILES_ALL  = Bb * KVH * NTILES_TOT;   // 512
constexpr int TILE_U4    = 1024;                    // uint4 per fragment tile (16KB)

// fragment-ordered K and V streams (fp16), written by prologue
__device__ uint4 g_kf[TILES_ALL * TILE_U4];   // 8 MB
__device__ uint4 g_vf[TILES_ALL * TILE_U4];   // 8 MB

// pack two fp32 -> fp16x2 {lo=x, hi=y}
__device__ __forceinline__ uint32_t pack2(float x, float y) {
    uint32_t d;
    asm("cvt.rn.f16x2.f32 %0, %1, %2;" : "=r"(d) : "f"(y), "f"(x));
    return d;
}

// elementwise exp2 on packed fp16x2
__device__ __forceinline__ uint32_t ex2x2(uint32_t x) {
    uint32_t r;
    asm("ex2.approx.f16x2 %0, %1;" : "=r"(r) : "r"(x));
    return r;
}

__device__ __forceinline__ uint4 ldg4(const uint4* p) {
    uint4 v;
    asm volatile("ld.global.nc.v4.u32 {%0,%1,%2,%3}, [%4];"
                 : "=r"(v.x), "=r"(v.y), "=r"(v.z), "=r"(v.w)
                 : "l"(__cvta_generic_to_global(p)));
    return v;
}

__device__ __forceinline__ void mma16816(float c[4],
                                         uint32_t a0, uint32_t a1, uint32_t a2, uint32_t a3,
                                         uint32_t b0, uint32_t b1) {
    asm volatile(
        "mma.sync.aligned.m16n8k16.row.col.f32.f16.f16.f32 "
        "{%0,%1,%2,%3}, {%4,%5,%6,%7}, {%8,%9}, {%0,%1,%2,%3};"
        : "+f"(c[0]), "+f"(c[1]), "+f"(c[2]), "+f"(c[3])
        : "r"(a0), "r"(a1), "r"(a2), "r"(a3), "r"(b0), "r"(b1));
}

} // namespace

// ───────── prologue: fp32 K/V -> fragment-ordered fp16 streams ─────────
// K layout: [c(4)][nt(8)][lane(32)] uint4 = {b0(kt=2c),b1(2c),b0(2c+1),b1(2c+1)}
//   where b0(nt,kt) = K[nt*8+rg][kt*16+2qq .. +1], b1 = same row, k+8.
// V layout: [kk(4)][m(8)][lane(32)] uint4 = {vb0(kk,2m),vb1(kk,2m),vb0(kk,2m+1),vb1(kk,2m+1)}
//   where vb0(kk,nb) = {V[kk*16+2qq][nb*8+rg], V[kk*16+2qq+1][nb*8+rg]}, vb1 = keys+8.
__global__ void __launch_bounds__(128)
frag_kernel(const float* __restrict__ k, const float* __restrict__ v)
{
    const int j   = blockIdx.x;
    const int kvh = blockIdx.y;
    const int b   = blockIdx.z;
    const int tid = threadIdx.x;

    __shared__ __half sk[64][132];
    __shared__ __half sv[64][132];

    const float* gK = k + ((size_t)(b * Ss + j * BC) * KVH + kvh) * HS;
    const float* gV = v + ((size_t)(b * Ss + j * BC) * KVH + kvh) * HS;
    for (int i = tid; i < BC * 32; i += 128) {
        int r = i >> 5, c4 = i & 31;
        float4 x = *(const float4*)(gK + (size_t)r * (KVH * HS) + c4 * 4);
        sk[r][c4 * 4 + 0] = __float2half_rn(x.x);
        sk[r][c4 * 4 + 1] = __float2half_rn(x.y);
        sk[r][c4 * 4 + 2] = __float2half_rn(x.z);
        sk[r][c4 * 4 + 3] = __float2half_rn(x.w);
        float4 y = *(const float4*)(gV + (size_t)r * (KVH * HS) + c4 * 4);
        sv[r][c4 * 4 + 0] = __float2half_rn(y.x);
        sv[r][c4 * 4 + 1] = __float2half_rn(y.y);
        sv[r][c4 * 4 + 2] = __float2half_rn(y.z);
        sv[r][c4 * 4 + 3] = __float2half_rn(y.w);
    }
    __syncthreads();

    const size_t tb = (size_t)((b * KVH + kvh) * NTILES_TOT + j) * TILE_U4;

    // K fragments
    for (int idx = tid; idx < TILE_U4; idx += 128) {
        int lane = idx & 31, qq = lane & 3, rg = lane >> 2;
        int cn = idx >> 5;                 // c*8 + nt
        int c = cn >> 3, nt = cn & 7;
        int row = nt * 8 + rg;
        uint32_t e[4];
        #pragma unroll
        for (int ee = 0; ee < 4; ++ee) {
            int kt  = 2 * c + (ee >> 1);
            int col = kt * 16 + (ee & 1) * 8 + 2 * qq;
            e[ee] = *(const uint32_t*)&sk[row][col];
        }
        g_kf[tb + idx] = make_uint4(e[0], e[1], e[2], e[3]);
    }

    // V fragments
    for (int idx = tid; idx < TILE_U4; idx += 128) {
        int lane = idx & 31, qq = lane & 3, rg = lane >> 2;
        int km = idx >> 5;                 // kk*8 + m
        int kk = km >> 3, m = km & 7;
        uint32_t e[4];
        #pragma unroll
        for (int ee = 0; ee < 4; ++ee) {
            int nb  = 2 * m + (ee >> 1);
            int key = kk * 16 + (ee & 1) * 8 + 2 * qq;
            int dim = nb * 8 + rg;
            uint32_t lo = (uint32_t)__half_as_ushort(sv[key][dim]);
            uint32_t hi = (uint32_t)__half_as_ushort(sv[key + 1][dim]);
            e[ee] = lo | (hi << 16);
        }
        g_vf[tb + idx] = make_uint4(e[0], e[1], e[2], e[3]);
    }
}

// ───────────────────── main attention: smem-free, barrier-free ─────────────────────
__global__ void __launch_bounds__(128, 3)
gqa_flash_f16d(const float* __restrict__ qg, float* __restrict__ outg)
{
    const int qt  = (int)gridDim.x - 1 - (int)blockIdx.x;   // heavy blocks first
    const int h   = blockIdx.y;
    const int b   = blockIdx.z;
    const int kvh = h >> 2;      // GROUP = 4

    const int tid  = threadIdx.x;
    const int lane = tid & 31;
    const int warp = tid >> 5;
    const int qq   = lane & 3;
    const int rg   = lane >> 2;
    const int q0   = qt * BR;
    const int rowA = warp * 16 + rg;
    const int ntiles = qt + 1;

    // 1/sqrt(128) * log2(e) — exp2 softmax, scale folded into Q
    const float SC = 0.0883883476483184405501f * 1.4426950408889634074f;

    // ones-column B fragment for row-sum mma: B[k][0] = 1, rest 0
    const uint32_t bone = (rg == 0) ? 0x3C003C00u : 0u;

    // ─── hoist Q fragments straight from fp32 gmem ───
    uint32_t qf[8][4];
    {
        const float* r0p = qg + ((size_t)(b * Ss + q0 + rowA) * NH + h) * HS;
        const float* r8p = r0p + (size_t)8 * NH * HS;
        #pragma unroll
        for (int kt = 0; kt < 8; ++kt) {
            int c = kt * 16 + 2 * qq;
            qf[kt][0] = pack2(r0p[c]     * SC, r0p[c + 1] * SC);
            qf[kt][1] = pack2(r8p[c]     * SC, r8p[c + 1] * SC);
            qf[kt][2] = pack2(r0p[c + 8] * SC, r0p[c + 9] * SC);
            qf[kt][3] = pack2(r8p[c + 8] * SC, r8p[c + 9] * SC);
        }
    }

    float o[16][4];
    #pragma unroll
    for (int i = 0; i < 16; ++i) { o[i][0] = o[i][1] = o[i][2] = o[i][3] = 0.f; }
    float lsum[4] = {0.f, 0.f, 0.f, 0.f};

    const size_t hb = (size_t)((b * KVH + kvh) * NTILES_TOT) * TILE_U4;

    for (int j = 0; j < ntiles; ++j) {
        const uint4* kf = g_kf + hb + (size_t)j * TILE_U4 + lane;
        const uint4* vf = g_vf + hb + (size_t)j * TILE_U4 + lane;

        // ─── S = Q · Kᵀ — LDG.128 fragments, 8 independent accumulators ───
        float s[8][4];
        #pragma unroll
        for (int i = 0; i < 8; ++i) { s[i][0] = s[i][1] = s[i][2] = s[i][3] = 0.f; }

        #pragma unroll
        for (int c = 0; c < 4; ++c) {
            uint4 ta[4], tb4[4];
            #pragma unroll
            for (int i = 0; i < 4; ++i) ta[i]  = ldg4(kf + (c * 8 + i) * 32);
            #pragma unroll
            for (int i = 0; i < 4; ++i) tb4[i] = ldg4(kf + (c * 8 + 4 + i) * 32);
            #pragma unroll
            for (int i = 0; i < 4; ++i) {
                mma16816(s[i], qf[2*c][0], qf[2*c][1], qf[2*c][2], qf[2*c][3],
                         ta[i].x, ta[i].y);
                mma16816(s[i], qf[2*c+1][0], qf[2*c+1][1], qf[2*c+1][2], qf[2*c+1][3],
                         ta[i].z, ta[i].w);
            }
            #pragma unroll
            for (int i = 0; i < 4; ++i) {
                mma16816(s[4+i], qf[2*c][0], qf[2*c][1], qf[2*c][2], qf[2*c][3],
                         tb4[i].x, tb4[i].y);
                mma16816(s[4+i], qf[2*c+1][0], qf[2*c+1][1], qf[2*c+1][2], qf[2*c+1][3],
                         tb4[i].z, tb4[i].w);
            }
        }

        // ─── softmax: mask (diag), fp16x2 pack, ex2.approx.f16x2 ───
        const bool diag = (j == ntiles - 1);
        uint32_t p[8][2];
        #pragma unroll
        for (int nt = 0; nt < 8; ++nt) {
            float s0 = s[nt][0], s1 = s[nt][1], s2 = s[nt][2], s3 = s[nt][3];
            if (diag) {
                int c = nt * 8 + 2 * qq;
                if (c     > rowA)     s0 = -1e30f;
                if (c + 1 > rowA)     s1 = -1e30f;
                if (c     > rowA + 8) s2 = -1e30f;
                if (c + 1 > rowA + 8) s3 = -1e30f;
            }
            p[nt][0] = ex2x2(pack2(s0, s1));
            p[nt][1] = ex2x2(pack2(s2, s3));
        }

        // ─── O += P · V ; l += P · 1  (tensor-pipe row sums) ───
        #pragma unroll
        for (int kk = 0; kk < 4; ++kk) {
            uint32_t a0 = p[2 * kk][0];
            uint32_t a1 = p[2 * kk][1];
            uint32_t a2 = p[2 * kk + 1][0];
            uint32_t a3 = p[2 * kk + 1][1];
            mma16816(lsum, a0, a1, a2, a3, bone, bone);
            uint4 ta[4], tb4[4];
            #pragma unroll
            for (int i = 0; i < 4; ++i) ta[i]  = ldg4(vf + (kk * 8 + i) * 32);
            #pragma unroll
            for (int i = 0; i < 4; ++i) tb4[i] = ldg4(vf + (kk * 8 + 4 + i) * 32);
            #pragma unroll
            for (int i = 0; i < 4; ++i) {
                mma16816(o[2*i],     a0, a1, a2, a3, ta[i].x, ta[i].y);
                mma16816(o[2*i + 1], a0, a1, a2, a3, ta[i].z, ta[i].w);
            }
            #pragma unroll
            for (int i = 0; i < 4; ++i) {
                mma16816(o[8 + 2*i],     a0, a1, a2, a3, tb4[i].x, tb4[i].y);
                mma16816(o[8 + 2*i + 1], a0, a1, a2, a3, tb4[i].z, tb4[i].w);
            }
        }
    }

    // ─── epilogue: broadcast row sums from quad leader, normalize, store ───
    const int src = lane & ~3;
    const float inv0 = 1.f / __shfl_sync(0xffffffffu, lsum[0], src);
    const float inv1 = 1.f / __shfl_sync(0xffffffffu, lsum[2], src);

    float* gO0 = outg + ((size_t)(b * Ss + q0 + rowA) * NH + h) * HS;
    float* gO1 = gO0 + (size_t)8 * NH * HS;
    #pragma unroll
    for (int nt = 0; nt < 16; ++nt) {
        int c = nt * 8 + 2 * qq;
        *(float2*)(gO0 + c) = make_float2(o[nt][0] * inv0, o[nt][1] * inv0);
        *(float2*)(gO1 + c) = make_float2(o[nt][2] * inv1, o[nt][3] * inv1);
    }
}

extern "C" void kernel_launch(void* const* d_in, const int* in_sizes, int n_in,
                              void* d_out, int out_size)
{
    (void)in_sizes; (void)n_in; (void)out_size;
    const float* q = (const float*)d_in[0];
    const float* k = (const float*)d_in[1];
    const float* v = (const float*)d_in[2];
    float* o = (float*)d_out;

    // 1) fp32 K/V -> fragment-ordered fp16 streams (one pass)
    dim3 pgrid(NTILES_TOT, KVH, Bb);   // (32, 8, 2)
    frag_kernel<<<pgrid, 128>>>(k, v);

    // 2) smem-free, barrier-free flash attention
    dim3 grid(Ss / BR, NH, Bb);        // (32, 32, 2) — inverted x -> heavy first
    gqa_flash_f16d<<<grid, 128>>>(q, o);
}

// round 8
// speedup vs baseline: 1.2942x; 1.2942x over previous
#include <cuda_runtime.h>
#include <cuda_fp16.h>
#include <cstdint>

namespace {

constexpr int NH  = 32;    // query heads
constexpr int HS  = 128;   // head size
constexpr int KVH = 8;     // kv heads
constexpr int Bb  = 2;
constexpr int Ss  = 2048;

constexpr int BR = 64;     // query rows per CTA
constexpr int BC = 64;     // keys per tile
constexpr int DK = 128;    // head dim

constexpr int RSB   = 272;          // smem row stride in bytes (136 fp16)
constexpr int TILEB = BC * RSB;     // 17408 (one K or V tile)
constexpr int BUFB  = 2 * TILEB;    // K+V buffer
constexpr int SMEM_BYTES = 2 * BUFB; // 69632 -> 3 CTAs/SM

constexpr size_t KV_ELEMS = (size_t)Bb * Ss * KVH * HS;  // 4,194,304

__device__ __half g_k16[KV_ELEMS];
__device__ __half g_v16[KV_ELEMS];

__device__ __forceinline__ uint32_t smem_u32(const void* p) {
    uint32_t a;
    asm("{ .reg .u64 t; cvta.to.shared.u64 t, %1; cvt.u32.u64 %0, t; }" : "=r"(a) : "l"(p));
    return a;
}

// pack two fp32 -> fp16x2 {lo=x, hi=y}
__device__ __forceinline__ uint32_t pack2(float x, float y) {
    uint32_t d;
    asm("cvt.rn.f16x2.f32 %0, %1, %2;" : "=r"(d) : "f"(y), "f"(x));
    return d;
}

// elementwise exp2 on packed fp16x2
__device__ __forceinline__ uint32_t ex2x2(uint32_t x) {
    uint32_t r;
    asm("ex2.approx.f16x2 %0, %1;" : "=r"(r) : "r"(x));
    return r;
}

__device__ __forceinline__ void cp16(uint32_t dst, const void* src) {
    asm volatile("cp.async.cg.shared.global [%0], [%1], 16;"
                 :: "r"(dst), "l"(__cvta_generic_to_global(src)) : "memory");
}
#define CP_COMMIT() asm volatile("cp.async.commit_group;" ::: "memory")
#define CP_WAIT(n)  asm volatile("cp.async.wait_group %0;" :: "n"(n) : "memory")

// 4x 8x8 b16 matrices, non-transposed
__device__ __forceinline__ void ldmx4(uint32_t& r0, uint32_t& r1, uint32_t& r2,
                                      uint32_t& r3, uint32_t a) {
    asm volatile("ldmatrix.sync.aligned.m8n8.x4.shared.b16 {%0,%1,%2,%3}, [%4];"
                 : "=r"(r0), "=r"(r1), "=r"(r2), "=r"(r3) : "r"(a));
}
// 4x 8x8 b16 matrices, transposed
__device__ __forceinline__ void ldmx4t(uint32_t& r0, uint32_t& r1, uint32_t& r2,
                                       uint32_t& r3, uint32_t a) {
    asm volatile("ldmatrix.sync.aligned.m8n8.x4.trans.shared.b16 {%0,%1,%2,%3}, [%4];"
                 : "=r"(r0), "=r"(r1), "=r"(r2), "=r"(r3) : "r"(a));
}

__device__ __forceinline__ void mma16816(float c[4],
                                         uint32_t a0, uint32_t a1, uint32_t a2, uint32_t a3,
                                         uint32_t b0, uint32_t b1) {
    asm volatile(
        "mma.sync.aligned.m16n8k16.row.col.f32.f16.f16.f32 "
        "{%0,%1,%2,%3}, {%4,%5,%6,%7}, {%8,%9}, {%0,%1,%2,%3};"
        : "+f"(c[0]), "+f"(c[1]), "+f"(c[2]), "+f"(c[3])
        : "r"(a0), "r"(a1), "r"(a2), "r"(a3), "r"(b0), "r"(b1));
}

} // namespace

// ───────────────────── prologue: fp32 K/V -> fp16 once ─────────────────────
__global__ void __launch_bounds__(256)
cvt_kv_kernel(const float* __restrict__ k, const float* __restrict__ v)
{
    size_t i = (size_t)blockIdx.x * blockDim.x + threadIdx.x;   // float4 index
    if (i < KV_ELEMS / 4) {
        float4 a = ((const float4*)k)[i];
        ((uint2*)g_k16)[i] = make_uint2(pack2(a.x, a.y), pack2(a.z, a.w));
        float4 b = ((const float4*)v)[i];
        ((uint2*)g_v16)[i] = make_uint2(pack2(b.x, b.y), pack2(b.z, b.w));
    }
}

// ───────────────────────────── main attention ─────────────────────────────
__global__ void __launch_bounds__(128, 3)
gqa_flash_f16e(const float* __restrict__ qg, float* __restrict__ outg)
{
    extern __shared__ __align__(16) char smem_raw[];
    const uint32_t sb = smem_u32(smem_raw);

    const int qt  = (int)gridDim.x - 1 - (int)blockIdx.x;   // heavy blocks first
    const int h   = blockIdx.y;
    const int b   = blockIdx.z;
    const int kvh = h >> 2;      // GROUP = 4

    const int tid  = threadIdx.x;
    const int lane = tid & 31;
    const int warp = tid >> 5;
    const int qq   = lane & 3;
    const int rg   = lane >> 2;
    const int q0   = qt * BR;
    const int rowA = warp * 16 + rg;
    const int ntiles = qt + 1;

    // 1/sqrt(128) * log2(e) — exp2 softmax, scale folded into Q
    const float SC = 0.0883883476483184405501f * 1.4426950408889634074f;

    // ones-column B fragment for row-sum mma: B[k][0] = 1, rest 0
    const uint32_t bone = (rg == 0) ? 0x3C003C00u : 0u;

    // cp.async staging of one K/V tile (fp16 gmem -> fp16 smem, 272B rows)
    const size_t kvbase = (size_t)(b * Ss) * KVH * HS + (size_t)kvh * HS;
    auto stage = [&](int j, int bufsel) {
        const __half* gk = g_k16 + kvbase + (size_t)(j * BC) * (KVH * HS);
        const __half* gv = g_v16 + kvbase + (size_t)(j * BC) * (KVH * HS);
        uint32_t dk = sb + bufsel * BUFB;
        uint32_t dv = dk + TILEB;
        const int rr = tid >> 4, cc = tid & 15;
        #pragma unroll
        for (int it = 0; it < 8; ++it) {
            int r = it * 8 + rr;
            cp16(dk + r * RSB + cc * 16, gk + (size_t)r * (KVH * HS) + cc * 8);
            cp16(dv + r * RSB + cc * 16, gv + (size_t)r * (KVH * HS) + cc * 8);
        }
    };

    stage(0, 0);
    CP_COMMIT();

    // ─── hoist Q fragments straight from fp32 gmem (overlaps with cp.async) ───
    uint32_t qf[8][4];
    {
        const float* r0p = qg + ((size_t)(b * Ss + q0 + rowA) * NH + h) * HS;
        const float* r8p = r0p + (size_t)8 * NH * HS;
        #pragma unroll
        for (int kt = 0; kt < 8; ++kt) {
            int c = kt * 16 + 2 * qq;
            qf[kt][0] = pack2(r0p[c]     * SC, r0p[c + 1] * SC);
            qf[kt][1] = pack2(r8p[c]     * SC, r8p[c + 1] * SC);
            qf[kt][2] = pack2(r0p[c + 8] * SC, r0p[c + 9] * SC);
            qf[kt][3] = pack2(r8p[c + 8] * SC, r8p[c + 9] * SC);
        }
    }

    float o[16][4];
    #pragma unroll
    for (int i = 0; i < 16; ++i) { o[i][0] = o[i][1] = o[i][2] = o[i][3] = 0.f; }
    float lsum[4] = {0.f, 0.f, 0.f, 0.f};   // row-sum C-frag (col 0 = Σ P)

    // per-warp smem operand addresses (loop-invariant)
    const uint32_t kaA0 = lane * RSB;              // key rows  0..31 (K frags)
    const uint32_t kaB0 = kaA0 + 32 * RSB;         // key rows 32..63
    const uint32_t va0  = (lane & 15) * RSB + (lane >> 4) * 16;   // V frags

    for (int j = 0; j < ntiles; ++j) {
        // stage(j) was committed a full tile ago -> wait is ~free
        CP_WAIT(0);
        __syncthreads();   // stage(j) visible to all; compute(j-1) done everywhere
        if (j + 1 < ntiles) {
            stage(j + 1, (j + 1) & 1);   // overlaps compute(j)
            CP_COMMIT();
        }

        const uint32_t kb = sb + (j & 1) * BUFB;
        const uint32_t vb = kb + TILEB;
        const uint32_t kaA = kb + kaA0;
        const uint32_t kaB = kb + kaB0;

        // ─── S = Q · Kᵀ — kt-outer: per k-chunk, 8 INDEPENDENT accumulator mmas ───
        float s[8][4];
        #pragma unroll
        for (int i = 0; i < 8; ++i) { s[i][0] = s[i][1] = s[i][2] = s[i][3] = 0.f; }

        #pragma unroll
        for (int kt = 0; kt < 8; ++kt) {
            uint32_t lA0, lA1, lA2, lA3, hA0, hA1, hA2, hA3;
            uint32_t lB0, lB1, lB2, lB3, hB0, hB1, hB2, hB3;
            ldmx4(lA0, lA1, lA2, lA3, kaA + kt * 32);        // nt0..3, k-low 8
            ldmx4(hA0, hA1, hA2, hA3, kaA + kt * 32 + 16);   // nt0..3, k-high 8
            ldmx4(lB0, lB1, lB2, lB3, kaB + kt * 32);        // nt4..7, k-low
            ldmx4(hB0, hB1, hB2, hB3, kaB + kt * 32 + 16);   // nt4..7, k-high
            mma16816(s[0], qf[kt][0], qf[kt][1], qf[kt][2], qf[kt][3], lA0, hA0);
            mma16816(s[1], qf[kt][0], qf[kt][1], qf[kt][2], qf[kt][3], lA1, hA1);
            mma16816(s[2], qf[kt][0], qf[kt][1], qf[kt][2], qf[kt][3], lA2, hA2);
            mma16816(s[3], qf[kt][0], qf[kt][1], qf[kt][2], qf[kt][3], lA3, hA3);
            mma16816(s[4], qf[kt][0], qf[kt][1], qf[kt][2], qf[kt][3], lB0, hB0);
            mma16816(s[5], qf[kt][0], qf[kt][1], qf[kt][2], qf[kt][3], lB1, hB1);
            mma16816(s[6], qf[kt][0], qf[kt][1], qf[kt][2], qf[kt][3], lB2, hB2);
            mma16816(s[7], qf[kt][0], qf[kt][1], qf[kt][2], qf[kt][3], lB3, hB3);
        }

        // ─── softmax: mask (diag), fp16x2 pack, ex2.approx.f16x2 ───
        const bool diag = (j == ntiles - 1);
        uint32_t p[8][2];
        #pragma unroll
        for (int nt = 0; nt < 8; ++nt) {
            float s0 = s[nt][0], s1 = s[nt][1], s2 = s[nt][2], s3 = s[nt][3];
            if (diag) {
                int c = nt * 8 + 2 * qq;
                if (c     > rowA)     s0 = -1e30f;
                if (c + 1 > rowA)     s1 = -1e30f;
                if (c     > rowA + 8) s2 = -1e30f;
                if (c + 1 > rowA + 8) s3 = -1e30f;
            }
            p[nt][0] = ex2x2(pack2(s0, s1));   // rows rowA
            p[nt][1] = ex2x2(pack2(s2, s3));   // rows rowA+8
        }

        // ─── O += P · V ; l += P · 1  (tensor-pipe row sums) ───
        #pragma unroll
        for (int kk = 0; kk < 4; ++kk) {
            uint32_t a0 = p[2 * kk][0];
            uint32_t a1 = p[2 * kk][1];
            uint32_t a2 = p[2 * kk + 1][0];
            uint32_t a3 = p[2 * kk + 1][1];
            mma16816(lsum, a0, a1, a2, a3, bone, bone);
            uint32_t va = vb + va0 + kk * 16 * RSB;
            #pragma unroll
            for (int ntp = 0; ntp < 8; ++ntp) {
                uint32_t b0, b1, b2, b3;
                ldmx4t(b0, b1, b2, b3, va + ntp * 32);   // V 8x8 tiles transposed
                mma16816(o[2 * ntp],     a0, a1, a2, a3, b0, b1);
                mma16816(o[2 * ntp + 1], a0, a1, a2, a3, b2, b3);
            }
        }
    }

    // ─── epilogue: broadcast row sums from quad leader, normalize, store ───
    const int src = lane & ~3;
    const float inv0 = 1.f / __shfl_sync(0xffffffffu, lsum[0], src);
    const float inv1 = 1.f / __shfl_sync(0xffffffffu, lsum[2], src);

    float* gO0 = outg + ((size_t)(b * Ss + q0 + rowA) * NH + h) * HS;
    float* gO1 = gO0 + (size_t)8 * NH * HS;
    #pragma unroll
    for (int nt = 0; nt < 16; ++nt) {
        int c = nt * 8 + 2 * qq;
        *(float2*)(gO0 + c) = make_float2(o[nt][0] * inv0, o[nt][1] * inv0);
        *(float2*)(gO1 + c) = make_float2(o[nt][2] * inv1, o[nt][3] * inv1);
    }
}

extern "C" void kernel_launch(void* const* d_in, const int* in_sizes, int n_in,
                              void* d_out, int out_size)
{
    (void)in_sizes; (void)n_in; (void)out_size;
    const float* q = (const float*)d_in[0];
    const float* k = (const float*)d_in[1];
    const float* v = (const float*)d_in[2];
    float* o = (float*)d_out;

    // 1) fp32 -> fp16 K/V pre-conversion (one pass, ~10us)
    cvt_kv_kernel<<<(int)(KV_ELEMS / 4 / 256), 256>>>(k, v);

    // 2) flash attention (single barrier per tile, hidden copy wait)
    cudaFuncSetAttribute(gqa_flash_f16e,
                         cudaFuncAttributeMaxDynamicSharedMemorySize, SMEM_BYTES);
    dim3 grid(Ss / BR, NH, Bb);   // (32, 32, 2) — inverted x -> heavy first
    gqa_flash_f16e<<<grid, 128, SMEM_BYTES>>>(q, o);
}

// round 9
// speedup vs baseline: 1.3946x; 1.0776x over previous
#include <cuda_runtime.h>
#include <cuda_fp16.h>
#include <cstdint>

namespace {

constexpr int NH  = 32;    // query heads
constexpr int HS  = 128;   // head size
constexpr int KVH = 8;     // kv heads
constexpr int Bb  = 2;
constexpr int Ss  = 2048;

constexpr int BR = 64;     // query rows per CTA
constexpr int BC = 64;     // keys per tile
constexpr int DK = 128;    // head dim

constexpr int NT         = Ss / BC;          // 32 tiles per (b,kvh)
constexpr int TILE_BYTES = BC * DK * 2;      // 16384 (fp16, 256B rows, swizzled)
constexpr int BUF_BYTES  = 2 * TILE_BYTES;   // K+V
constexpr int SMEM_BYTES = 1024 + 2 * BUF_BYTES;  // 66560 -> 3 CTAs/SM

// pre-swizzled fp16 tile images, written by prologue (8 MB each)
__device__ __align__(16) uint8_t g_kt[(size_t)Bb * KVH * NT * TILE_BYTES];
__device__ __align__(16) uint8_t g_vt[(size_t)Bb * KVH * NT * TILE_BYTES];

__device__ __forceinline__ uint32_t smem_u32(const void* p) {
    uint32_t a;
    asm("{ .reg .u64 t; cvta.to.shared.u64 t, %1; cvt.u32.u64 %0, t; }" : "=r"(a) : "l"(p));
    return a;
}

// pack two fp32 -> fp16x2 {lo=x, hi=y}
__device__ __forceinline__ uint32_t pack2(float x, float y) {
    uint32_t d;
    asm("cvt.rn.f16x2.f32 %0, %1, %2;" : "=r"(d) : "f"(y), "f"(x));
    return d;
}

// elementwise exp2 on packed fp16x2
__device__ __forceinline__ uint32_t ex2x2(uint32_t x) {
    uint32_t r;
    asm("ex2.approx.f16x2 %0, %1;" : "=r"(r) : "r"(x));
    return r;
}

// 4x 8x8 b16 matrices, non-transposed
__device__ __forceinline__ void ldmx4(uint32_t& r0, uint32_t& r1, uint32_t& r2,
                                      uint32_t& r3, uint32_t a) {
    asm volatile("ldmatrix.sync.aligned.m8n8.x4.shared.b16 {%0,%1,%2,%3}, [%4];"
                 : "=r"(r0), "=r"(r1), "=r"(r2), "=r"(r3) : "r"(a));
}
// 4x 8x8 b16 matrices, transposed
__device__ __forceinline__ void ldmx4t(uint32_t& r0, uint32_t& r1, uint32_t& r2,
                                       uint32_t& r3, uint32_t a) {
    asm volatile("ldmatrix.sync.aligned.m8n8.x4.trans.shared.b16 {%0,%1,%2,%3}, [%4];"
                 : "=r"(r0), "=r"(r1), "=r"(r2), "=r"(r3) : "r"(a));
}

__device__ __forceinline__ void mma16816(float c[4],
                                         uint32_t a0, uint32_t a1, uint32_t a2, uint32_t a3,
                                         uint32_t b0, uint32_t b1) {
    asm volatile(
        "mma.sync.aligned.m16n8k16.row.col.f32.f16.f16.f32 "
        "{%0,%1,%2,%3}, {%4,%5,%6,%7}, {%8,%9}, {%0,%1,%2,%3};"
        : "+f"(c[0]), "+f"(c[1]), "+f"(c[2]), "+f"(c[3])
        : "r"(a0), "r"(a1), "r"(a2), "r"(a3), "r"(b0), "r"(b1));
}

#define MB_INIT(mb, c) \
    asm volatile("mbarrier.init.shared.b64 [%0], %1;" :: "r"(mb), "r"(c) : "memory")
#define MB_EXPECT(mb, bytes) \
    asm volatile("mbarrier.arrive.expect_tx.shared.b64 _, [%0], %1;" \
                 :: "r"(mb), "r"(bytes) : "memory")
#define MB_WAIT(mb, ph) do {                                                   \
    uint32_t _m = (mb), _p = (ph), _d;                                         \
    asm volatile("{ .reg .pred p; mbarrier.try_wait.parity.acquire.cta.shared::cta.b64 p, [%1], %2; selp.b32 %0, 1, 0, p; }" \
                 : "=r"(_d) : "r"(_m), "r"(_p) : "memory");                    \
    if (!_d) {                                                                 \
        asm volatile("{ .reg .pred P1; WL_%=: mbarrier.try_wait.parity.acquire.cta.shared::cta.b64 P1, [%0], %1, 0x989680; @P1 bra.uni WD_%=; bra.uni WL_%=; WD_%=: }" \
                     :: "r"(_m), "r"(_p) : "memory");                          \
    }                                                                          \
} while (0)

#define BULK(dst, src, sz, mb) \
    asm volatile("cp.async.bulk.shared::cta.global.mbarrier::complete_tx::bytes [%0], [%1], %2, [%3];" \
                 :: "r"(dst), "l"(__cvta_generic_to_global(src)), "r"(sz), "r"(mb) : "memory")

} // namespace

// ───────── prologue: fp32 K/V -> pre-swizzled fp16 tile images ─────────
// element (row r, dim c) of a 64x128 tile lives at byte:
//   r*256 + (((c>>3) ^ (r&7)) << 4) + (c&7)*2
__global__ void __launch_bounds__(128)
pack_kv(const float* __restrict__ k, const float* __restrict__ v)
{
    const int j   = blockIdx.x;
    const int kvh = blockIdx.y;
    const int b   = blockIdx.z;

    const float* gK = k + ((size_t)(b * Ss + j * BC) * KVH + kvh) * HS;
    const float* gV = v + ((size_t)(b * Ss + j * BC) * KVH + kvh) * HS;
    uint8_t* tK = g_kt + (size_t)((b * KVH + kvh) * NT + j) * TILE_BYTES;
    uint8_t* tV = g_vt + (size_t)((b * KVH + kvh) * NT + j) * TILE_BYTES;

    for (int idx = threadIdx.x; idx < BC * (DK / 2); idx += 128) {
        int r = idx >> 6, c = (idx & 63) * 2;
        uint32_t off = r * 256 + ((((c >> 3) ^ (r & 7)) & 15) << 4) + (c & 7) * 2;
        float2 a = *(const float2*)(gK + (size_t)r * (KVH * HS) + c);
        *(uint32_t*)(tK + off) = pack2(a.x, a.y);
        float2 w = *(const float2*)(gV + (size_t)r * (KVH * HS) + c);
        *(uint32_t*)(tV + off) = pack2(w.x, w.y);
    }
}

// ───────────────────────────── main attention ─────────────────────────────
__global__ void __launch_bounds__(128, 3)
gqa_flash_f16f(const float* __restrict__ qg, float* __restrict__ outg)
{
    extern __shared__ __align__(16) char smem_raw[];
    const uint32_t sb = smem_u32(smem_raw);

    const int qt  = (int)gridDim.x - 1 - (int)blockIdx.x;   // heavy blocks first
    const int h   = blockIdx.y;
    const int b   = blockIdx.z;
    const int kvh = h >> 2;      // GROUP = 4

    const int tid  = threadIdx.x;
    const int lane = tid & 31;
    const int warp = tid >> 5;
    const int qq   = lane & 3;
    const int rg   = lane >> 2;
    const int lx   = lane & 7;
    const int q0   = qt * BR;
    const int rowA = warp * 16 + rg;
    const int ntiles = qt + 1;

    // 1/sqrt(128) * log2(e) — exp2 softmax, scale folded into Q
    const float SC = 0.0883883476483184405501f * 1.4426950408889634074f;
    // ones-column B fragment for row-sum mma
    const uint32_t bone = (rg == 0) ? 0x3C003C00u : 0u;

    const size_t hb = (size_t)((b * KVH + kvh) * NT) * TILE_BYTES;

    if (tid == 0) { MB_INIT(sb, 1); MB_INIT(sb + 8, 1); }
    __syncthreads();
    if (tid == 0) {
        MB_EXPECT(sb, BUF_BYTES);
        BULK(sb + 1024,              g_kt + hb, TILE_BYTES, sb);
        BULK(sb + 1024 + TILE_BYTES, g_vt + hb, TILE_BYTES, sb);
    }

    // ─── hoist Q fragments straight from fp32 gmem (overlaps with bulk copy) ───
    uint32_t qf[8][4];
    {
        const float* r0p = qg + ((size_t)(b * Ss + q0 + rowA) * NH + h) * HS;
        const float* r8p = r0p + (size_t)8 * NH * HS;
        #pragma unroll
        for (int kt = 0; kt < 8; ++kt) {
            int c = kt * 16 + 2 * qq;
            qf[kt][0] = pack2(r0p[c]     * SC, r0p[c + 1] * SC);
            qf[kt][1] = pack2(r8p[c]     * SC, r8p[c + 1] * SC);
            qf[kt][2] = pack2(r0p[c + 8] * SC, r0p[c + 9] * SC);
            qf[kt][3] = pack2(r8p[c + 8] * SC, r8p[c + 9] * SC);
        }
    }

    float o[16][4];
    #pragma unroll
    for (int i = 0; i < 16; ++i) { o[i][0] = o[i][1] = o[i][2] = o[i][3] = 0.f; }
    float lsum[4] = {0.f, 0.f, 0.f, 0.f};

    for (int j = 0; j < ntiles; ++j) {
        __syncthreads();   // compute(j-1) done everywhere: buffer (j+1)&1 free
        if (j + 1 < ntiles && tid == 0) {
            const int s = (j + 1) & 1;
            const uint32_t mb = sb + 8 * s;
            const uint32_t dk = sb + 1024 + s * BUF_BYTES;
            MB_EXPECT(mb, BUF_BYTES);
            BULK(dk,              g_kt + hb + (size_t)(j + 1) * TILE_BYTES, TILE_BYTES, mb);
            BULK(dk + TILE_BYTES, g_vt + hb + (size_t)(j + 1) * TILE_BYTES, TILE_BYTES, mb);
        }
        MB_WAIT(sb + 8 * (j & 1), (j >> 1) & 1);   // stage(j) arrived (armed a tile ago)

        const uint32_t kb  = sb + 1024 + (j & 1) * BUF_BYTES;
        const uint32_t vb  = kb + TILE_BYTES;
        const uint32_t kaA = kb + lane * 256;      // key rows  0..31
        const uint32_t kaB = kaA + 32 * 256;       // key rows 32..63
        const bool diag = (j == ntiles - 1);
        const bool doB  = !diag || (warp >= 2);    // cols 32..63 fully masked for warps 0,1

        // ─── S = Q · Kᵀ — kt-outer, independent accumulators, swizzled LDSM ───
        float s[8][4];
        #pragma unroll
        for (int i = 0; i < 8; ++i) { s[i][0] = s[i][1] = s[i][2] = s[i][3] = 0.f; }

        #pragma unroll
        for (int kt = 0; kt < 8; ++kt) {
            const uint32_t oL = (uint32_t)(((2 * kt)     ^ lx) << 4);
            const uint32_t oH = (uint32_t)(((2 * kt + 1) ^ lx) << 4);
            uint32_t lA0, lA1, lA2, lA3, hA0, hA1, hA2, hA3;
            ldmx4(lA0, lA1, lA2, lA3, kaA + oL);
            ldmx4(hA0, hA1, hA2, hA3, kaA + oH);
            mma16816(s[0], qf[kt][0], qf[kt][1], qf[kt][2], qf[kt][3], lA0, hA0);
            mma16816(s[1], qf[kt][0], qf[kt][1], qf[kt][2], qf[kt][3], lA1, hA1);
            mma16816(s[2], qf[kt][0], qf[kt][1], qf[kt][2], qf[kt][3], lA2, hA2);
            mma16816(s[3], qf[kt][0], qf[kt][1], qf[kt][2], qf[kt][3], lA3, hA3);
            if (doB) {
                uint32_t lB0, lB1, lB2, lB3, hB0, hB1, hB2, hB3;
                ldmx4(lB0, lB1, lB2, lB3, kaB + oL);
                ldmx4(hB0, hB1, hB2, hB3, kaB + oH);
                mma16816(s[4], qf[kt][0], qf[kt][1], qf[kt][2], qf[kt][3], lB0, hB0);
                mma16816(s[5], qf[kt][0], qf[kt][1], qf[kt][2], qf[kt][3], lB1, hB1);
                mma16816(s[6], qf[kt][0], qf[kt][1], qf[kt][2], qf[kt][3], lB2, hB2);
                mma16816(s[7], qf[kt][0], qf[kt][1], qf[kt][2], qf[kt][3], lB3, hB3);
            }
        }

        // ─── softmax: mask (diag), fp16x2 pack, ex2.approx.f16x2 ───
        uint32_t p[8][2];
        #pragma unroll
        for (int nt = 0; nt < 8; ++nt) {
            if (nt >= 4 && !doB) continue;   // unused on diag for warps 0,1
            float s0 = s[nt][0], s1 = s[nt][1], s2 = s[nt][2], s3 = s[nt][3];
            if (diag) {
                int c = nt * 8 + 2 * qq;
                if (c     > rowA)     s0 = -1e30f;
                if (c + 1 > rowA)     s1 = -1e30f;
                if (c     > rowA + 8) s2 = -1e30f;
                if (c + 1 > rowA + 8) s3 = -1e30f;
            }
            p[nt][0] = ex2x2(pack2(s0, s1));   // rows rowA
            p[nt][1] = ex2x2(pack2(s2, s3));   // rows rowA+8
        }

        // ─── O += P · V ; l += P · 1 — skip fully-masked key chunks on diag ───
        #pragma unroll
        for (int kk = 0; kk < 4; ++kk) {
            if (diag && kk > warp) break;      // P exactly 0 there
            uint32_t a0 = p[2 * kk][0];
            uint32_t a1 = p[2 * kk][1];
            uint32_t a2 = p[2 * kk + 1][0];
            uint32_t a3 = p[2 * kk + 1][1];
            mma16816(lsum, a0, a1, a2, a3, bone, bone);
            const uint32_t vrow = vb + (uint32_t)(kk * 16 + (lane & 15)) * 256;
            const uint32_t vch  = (uint32_t)(lane >> 4);
            #pragma unroll
            for (int ntp = 0; ntp < 8; ++ntp) {
                uint32_t b0, b1, b2, b3;
                ldmx4t(b0, b1, b2, b3, vrow + (((vch + 2 * ntp) ^ lx) << 4));
                mma16816(o[2 * ntp],     a0, a1, a2, a3, b0, b1);
                mma16816(o[2 * ntp + 1], a0, a1, a2, a3, b2, b3);
            }
        }
    }

    // ─── epilogue: broadcast row sums from quad leader, normalize, store ───
    const int src = lane & ~3;
    const float inv0 = 1.f / __shfl_sync(0xffffffffu, lsum[0], src);
    const float inv1 = 1.f / __shfl_sync(0xffffffffu, lsum[2], src);

    float* gO0 = outg + ((size_t)(b * Ss + q0 + rowA) * NH + h) * HS;
    float* gO1 = gO0 + (size_t)8 * NH * HS;
    #pragma unroll
    for (int nt = 0; nt < 16; ++nt) {
        int c = nt * 8 + 2 * qq;
        *(float2*)(gO0 + c) = make_float2(o[nt][0] * inv0, o[nt][1] * inv0);
        *(float2*)(gO1 + c) = make_float2(o[nt][2] * inv1, o[nt][3] * inv1);
    }
}

extern "C" void kernel_launch(void* const* d_in, const int* in_sizes, int n_in,
                              void* d_out, int out_size)
{
    (void)in_sizes; (void)n_in; (void)out_size;
    const float* q = (const float*)d_in[0];
    const float* k = (const float*)d_in[1];
    const float* v = (const float*)d_in[2];
    float* o = (float*)d_out;

    // 1) fp32 K/V -> pre-swizzled fp16 tile images (one pass, ~10us)
    dim3 pgrid(NT, KVH, Bb);   // (32, 8, 2)
    pack_kv<<<pgrid, 128>>>(k, v);

    // 2) flash attention with bulk-copy staging
    cudaFuncSetAttribute(gqa_flash_f16f,
                         cudaFuncAttributeMaxDynamicSharedMemorySize, SMEM_BYTES);
    dim3 grid(Ss / BR, NH, Bb);   // (32, 32, 2) — inverted x -> heavy first
    gqa_flash_f16f<<<grid, 128, SMEM_BYTES>>>(q, o);
}

// round 11
// speedup vs baseline: 1.6217x; 1.1628x over previous
#include <cuda_runtime.h>
#include <cuda_fp16.h>
#include <cstdint>

namespace {

constexpr int NH  = 32;    // query heads
constexpr int HS  = 128;   // head size
constexpr int KVH = 8;     // kv heads
constexpr int Bb  = 2;
constexpr int Ss  = 2048;

constexpr int BR = 64;     // query rows per CTA
constexpr int BC = 64;     // keys per tile
constexpr int DK = 128;    // head dim

constexpr int NT         = Ss / BC;          // 32 tiles per (b,kvh)
constexpr int TILE_BYTES = BC * DK * 2;      // 16384 (fp16, 256B rows, swizzled)
constexpr int BUF_BYTES  = 2 * TILE_BYTES;   // K+V
constexpr int SMEM_BYTES = 1024 + 2 * BUF_BYTES;  // 66560 -> 3 CTAs/SM

// pre-swizzled fp16 tile images, written by prologue (8 MB each)
__device__ __align__(16) uint8_t g_kt[(size_t)Bb * KVH * NT * TILE_BYTES];
__device__ __align__(16) uint8_t g_vt[(size_t)Bb * KVH * NT * TILE_BYTES];

__device__ __forceinline__ uint32_t smem_u32(const void* p) {
    uint32_t a;
    asm("{ .reg .u64 t; cvta.to.shared.u64 t, %1; cvt.u32.u64 %0, t; }" : "=r"(a) : "l"(p));
    return a;
}

// pack two fp32 -> fp16x2 {lo=x, hi=y}
__device__ __forceinline__ uint32_t pack2(float x, float y) {
    uint32_t d;
    asm("cvt.rn.f16x2.f32 %0, %1, %2;" : "=r"(d) : "f"(y), "f"(x));
    return d;
}

// elementwise exp2 on packed fp16x2
__device__ __forceinline__ uint32_t ex2x2(uint32_t x) {
    uint32_t r;
    asm("ex2.approx.f16x2 %0, %1;" : "=r"(r) : "r"(x));
    return r;
}

// 4x 8x8 b16 matrices, non-transposed
__device__ __forceinline__ void ldmx4(uint32_t& r0, uint32_t& r1, uint32_t& r2,
                                      uint32_t& r3, uint32_t a) {
    asm volatile("ldmatrix.sync.aligned.m8n8.x4.shared.b16 {%0,%1,%2,%3}, [%4];"
                 : "=r"(r0), "=r"(r1), "=r"(r2), "=r"(r3) : "r"(a));
}
// 4x 8x8 b16 matrices, transposed
__device__ __forceinline__ void ldmx4t(uint32_t& r0, uint32_t& r1, uint32_t& r2,
                                       uint32_t& r3, uint32_t a) {
    asm volatile("ldmatrix.sync.aligned.m8n8.x4.trans.shared.b16 {%0,%1,%2,%3}, [%4];"
                 : "=r"(r0), "=r"(r1), "=r"(r2), "=r"(r3) : "r"(a));
}

__device__ __forceinline__ void mma16816(float c[4],
                                         uint32_t a0, uint32_t a1, uint32_t a2, uint32_t a3,
                                         uint32_t b0, uint32_t b1) {
    asm volatile(
        "mma.sync.aligned.m16n8k16.row.col.f32.f16.f16.f32 "
        "{%0,%1,%2,%3}, {%4,%5,%6,%7}, {%8,%9}, {%0,%1,%2,%3};"
        : "+f"(c[0]), "+f"(c[1]), "+f"(c[2]), "+f"(c[3])
        : "r"(a0), "r"(a1), "r"(a2), "r"(a3), "r"(b0), "r"(b1));
}

#define MB_INIT(mb, c) \
    asm volatile("mbarrier.init.shared.b64 [%0], %1;" :: "r"(mb), "r"(c) : "memory")
#define MB_EXPECT(mb, bytes) \
    asm volatile("mbarrier.arrive.expect_tx.shared.b64 _, [%0], %1;" \
                 :: "r"(mb), "r"(bytes) : "memory")
#define MB_WAIT(mb, ph) do {                                                   \
    uint32_t _m = (mb), _p = (ph), _d;                                         \
    asm volatile("{ .reg .pred p; mbarrier.try_wait.parity.acquire.cta.shared::cta.b64 p, [%1], %2; selp.b32 %0, 1, 0, p; }" \
                 : "=r"(_d) : "r"(_m), "r"(_p) : "memory");                    \
    if (!_d) {                                                                 \
        asm volatile("{ .reg .pred P1; WL_%=: mbarrier.try_wait.parity.acquire.cta.shared::cta.b64 P1, [%0], %1, 0x989680; @P1 bra.uni WD_%=; bra.uni WL_%=; WD_%=: }" \
                     :: "r"(_m), "r"(_p) : "memory");                          \
    }                                                                          \
} while (0)

#define BULK(dst, src, sz, mb) \
    asm volatile("cp.async.bulk.shared::cta.global.mbarrier::complete_tx::bytes [%0], [%1], %2, [%3];" \
                 :: "r"(dst), "l"(__cvta_generic_to_global(src)), "r"(sz), "r"(mb) : "memory")

} // namespace

// ───────── prologue: fp32 K/V -> pre-swizzled fp16 tile images ─────────
// Output-centric, fully coalesced: output 16B chunk (r, ch) holds input cols
// [(ch ^ (r&7))*8, +8) of row r.  LDG.128 x4 + STG.128 x2 per iteration.
__global__ void __launch_bounds__(256)
pack_kv(const float* __restrict__ k, const float* __restrict__ v)
{
    const int j   = blockIdx.x;
    const int kvh = blockIdx.y;
    const int b   = blockIdx.z;

    const float* gK = k + ((size_t)(b * Ss + j * BC) * KVH + kvh) * HS;
    const float* gV = v + ((size_t)(b * Ss + j * BC) * KVH + kvh) * HS;
    uint4* tK = (uint4*)(g_kt + (size_t)((b * KVH + kvh) * NT + j) * TILE_BYTES);
    uint4* tV = (uint4*)(g_vt + (size_t)((b * KVH + kvh) * NT + j) * TILE_BYTES);

    #pragma unroll
    for (int u = threadIdx.x; u < BC * 16; u += 256) {
        int r  = u >> 4;
        int ch = u & 15;
        int c0 = (ch ^ (r & 7)) << 3;
        const float* rk = gK + (size_t)r * (KVH * HS) + c0;
        float4 a0 = *(const float4*)(rk);
        float4 a1 = *(const float4*)(rk + 4);
        tK[u] = make_uint4(pack2(a0.x, a0.y), pack2(a0.z, a0.w),
                           pack2(a1.x, a1.y), pack2(a1.z, a1.w));
        const float* rv = gV + (size_t)r * (KVH * HS) + c0;
        float4 w0 = *(const float4*)(rv);
        float4 w1 = *(const float4*)(rv + 4);
        tV[u] = make_uint4(pack2(w0.x, w0.y), pack2(w0.z, w0.w),
                           pack2(w1.x, w1.y), pack2(w1.z, w1.w));
    }
}

// ───────────────────────────── main attention ─────────────────────────────
// smem: [0,8)=full0 [8,16)=full1; data @1024. Sync: __syncthreads per tile
// (proven R9 pipeline), diag tile split out for a branch-free steady loop.
__global__ void __launch_bounds__(128, 3)
gqa_flash_f16h(const float* __restrict__ qg, float* __restrict__ outg)
{
    extern __shared__ __align__(16) char smem_raw[];
    const uint32_t sb = smem_u32(smem_raw);

    const int qt  = (int)gridDim.x - 1 - (int)blockIdx.x;   // heavy blocks first
    const int h   = blockIdx.y;
    const int b   = blockIdx.z;
    const int kvh = h >> 2;      // GROUP = 4

    const int tid  = threadIdx.x;
    const int lane = tid & 31;
    const int warp = tid >> 5;
    const int qq   = lane & 3;
    const int rg   = lane >> 2;
    const int lx   = lane & 7;
    const int q0   = qt * BR;
    const int rowA = warp * 16 + rg;
    const int ntiles = qt + 1;
    const int nlast  = ntiles - 1;   // diagonal tile index

    // 1/sqrt(128) * log2(e) — exp2 softmax, scale folded into Q
    const float SC = 0.0883883476483184405501f * 1.4426950408889634074f;
    // ones-column B fragment for row-sum mma
    const uint32_t bone = (rg == 0) ? 0x3C003C00u : 0u;

    const size_t hb = (size_t)((b * KVH + kvh) * NT) * TILE_BYTES;

    if (tid == 0) { MB_INIT(sb, 1); MB_INIT(sb + 8, 1); }
    __syncthreads();
    if (tid == 0) {
        MB_EXPECT(sb, BUF_BYTES);
        BULK(sb + 1024,              g_kt + hb, TILE_BYTES, sb);
        BULK(sb + 1024 + TILE_BYTES, g_vt + hb, TILE_BYTES, sb);
    }

    // ─── hoist Q fragments straight from fp32 gmem (overlaps with bulk copy) ───
    uint32_t qf[8][4];
    {
        const float* r0p = qg + ((size_t)(b * Ss + q0 + rowA) * NH + h) * HS;
        const float* r8p = r0p + (size_t)8 * NH * HS;
        #pragma unroll
        for (int kt = 0; kt < 8; ++kt) {
            int c = kt * 16 + 2 * qq;
            qf[kt][0] = pack2(r0p[c]     * SC, r0p[c + 1] * SC);
            qf[kt][1] = pack2(r8p[c]     * SC, r8p[c + 1] * SC);
            qf[kt][2] = pack2(r0p[c + 8] * SC, r0p[c + 9] * SC);
            qf[kt][3] = pack2(r8p[c + 8] * SC, r8p[c + 9] * SC);
        }
    }

    float o[16][4];
    #pragma unroll
    for (int i = 0; i < 16; ++i) { o[i][0] = o[i][1] = o[i][2] = o[i][3] = 0.f; }
    float lsum[4] = {0.f, 0.f, 0.f, 0.f};

    // ─── steady-state tiles (mask-free, branch-free body) ───
    for (int j = 0; j < nlast; ++j) {
        __syncthreads();   // compute(j-1) done everywhere: buffer (j+1)&1 free
        if (tid == 0) {
            const int jn = j + 1;                 // jn <= nlast always
            const int s  = jn & 1;
            const uint32_t mb = sb + 8 * s;
            const uint32_t dk = sb + 1024 + s * BUF_BYTES;
            MB_EXPECT(mb, BUF_BYTES);
            BULK(dk,              g_kt + hb + (size_t)jn * TILE_BYTES, TILE_BYTES, mb);
            BULK(dk + TILE_BYTES, g_vt + hb + (size_t)jn * TILE_BYTES, TILE_BYTES, mb);
        }
        MB_WAIT(sb + 8 * (j & 1), (j >> 1) & 1);   // stage(j) arrived

        const uint32_t kb  = sb + 1024 + (j & 1) * BUF_BYTES;
        const uint32_t vb  = kb + TILE_BYTES;
        const uint32_t kaA = kb + lane * 256;      // key rows  0..31
        const uint32_t kaB = kaA + 32 * 256;       // key rows 32..63

        float s[8][4];
        #pragma unroll
        for (int i = 0; i < 8; ++i) { s[i][0] = s[i][1] = s[i][2] = s[i][3] = 0.f; }

        #pragma unroll
        for (int kt = 0; kt < 8; ++kt) {
            const uint32_t oL = (uint32_t)(((2 * kt)     ^ lx) << 4);
            const uint32_t oH = (uint32_t)(((2 * kt + 1) ^ lx) << 4);
            uint32_t lA0, lA1, lA2, lA3, hA0, hA1, hA2, hA3;
            uint32_t lB0, lB1, lB2, lB3, hB0, hB1, hB2, hB3;
            ldmx4(lA0, lA1, lA2, lA3, kaA + oL);
            ldmx4(hA0, hA1, hA2, hA3, kaA + oH);
            ldmx4(lB0, lB1, lB2, lB3, kaB + oL);
            ldmx4(hB0, hB1, hB2, hB3, kaB + oH);
            mma16816(s[0], qf[kt][0], qf[kt][1], qf[kt][2], qf[kt][3], lA0, hA0);
            mma16816(s[1], qf[kt][0], qf[kt][1], qf[kt][2], qf[kt][3], lA1, hA1);
            mma16816(s[2], qf[kt][0], qf[kt][1], qf[kt][2], qf[kt][3], lA2, hA2);
            mma16816(s[3], qf[kt][0], qf[kt][1], qf[kt][2], qf[kt][3], lA3, hA3);
            mma16816(s[4], qf[kt][0], qf[kt][1], qf[kt][2], qf[kt][3], lB0, hB0);
            mma16816(s[5], qf[kt][0], qf[kt][1], qf[kt][2], qf[kt][3], lB1, hB1);
            mma16816(s[6], qf[kt][0], qf[kt][1], qf[kt][2], qf[kt][3], lB2, hB2);
            mma16816(s[7], qf[kt][0], qf[kt][1], qf[kt][2], qf[kt][3], lB3, hB3);
        }

        uint32_t p[8][2];
        #pragma unroll
        for (int nt = 0; nt < 8; ++nt) {
            p[nt][0] = ex2x2(pack2(s[nt][0], s[nt][1]));
            p[nt][1] = ex2x2(pack2(s[nt][2], s[nt][3]));
        }

        #pragma unroll
        for (int kk = 0; kk < 4; ++kk) {
            uint32_t a0 = p[2 * kk][0];
            uint32_t a1 = p[2 * kk][1];
            uint32_t a2 = p[2 * kk + 1][0];
            uint32_t a3 = p[2 * kk + 1][1];
            mma16816(lsum, a0, a1, a2, a3, bone, bone);
            const uint32_t vrow = vb + (uint32_t)(kk * 16 + (lane & 15)) * 256;
            const uint32_t vch  = (uint32_t)(lane >> 4);
            #pragma unroll
            for (int ntp = 0; ntp < 8; ++ntp) {
                uint32_t b0, b1, b2, b3;
                ldmx4t(b0, b1, b2, b3, vrow + (((vch + 2 * ntp) ^ lx) << 4));
                mma16816(o[2 * ntp],     a0, a1, a2, a3, b0, b1);
                mma16816(o[2 * ntp + 1], a0, a1, a2, a3, b2, b3);
            }
        }
    }

    // ─── diagonal tile (causal mask + work skip) ───
    {
        const int j = nlast;
        MB_WAIT(sb + 8 * (j & 1), (j >> 1) & 1);

        const uint32_t kb  = sb + 1024 + (j & 1) * BUF_BYTES;
        const uint32_t vb  = kb + TILE_BYTES;
        const uint32_t kaA = kb + lane * 256;
        const uint32_t kaB = kaA + 32 * 256;
        const bool doB = (warp >= 2);   // cols 32..63 fully masked for warps 0,1

        float s[8][4];
        #pragma unroll
        for (int i = 0; i < 8; ++i) { s[i][0] = s[i][1] = s[i][2] = s[i][3] = 0.f; }

        #pragma unroll
        for (int kt = 0; kt < 8; ++kt) {
            const uint32_t oL = (uint32_t)(((2 * kt)     ^ lx) << 4);
            const uint32_t oH = (uint32_t)(((2 * kt + 1) ^ lx) << 4);
            uint32_t lA0, lA1, lA2, lA3, hA0, hA1, hA2, hA3;
            ldmx4(lA0, lA1, lA2, lA3, kaA + oL);
            ldmx4(hA0, hA1, hA2, hA3, kaA + oH);
            mma16816(s[0], qf[kt][0], qf[kt][1], qf[kt][2], qf[kt][3], lA0, hA0);
            mma16816(s[1], qf[kt][0], qf[kt][1], qf[kt][2], qf[kt][3], lA1, hA1);
            mma16816(s[2], qf[kt][0], qf[kt][1], qf[kt][2], qf[kt][3], lA2, hA2);
            mma16816(s[3], qf[kt][0], qf[kt][1], qf[kt][2], qf[kt][3], lA3, hA3);
            if (doB) {
                uint32_t lB0, lB1, lB2, lB3, hB0, hB1, hB2, hB3;
                ldmx4(lB0, lB1, lB2, lB3, kaB + oL);
                ldmx4(hB0, hB1, hB2, hB3, kaB + oH);
                mma16816(s[4], qf[kt][0], qf[kt][1], qf[kt][2], qf[kt][3], lB0, hB0);
                mma16816(s[5], qf[kt][0], qf[kt][1], qf[kt][2], qf[kt][3], lB1, hB1);
                mma16816(s[6], qf[kt][0], qf[kt][1], qf[kt][2], qf[kt][3], lB2, hB2);
                mma16816(s[7], qf[kt][0], qf[kt][1], qf[kt][2], qf[kt][3], lB3, hB3);
            }
        }

        uint32_t p[8][2];
        #pragma unroll
        for (int nt = 0; nt < 8; ++nt) {
            if (nt >= 4 && !doB) continue;
            float s0 = s[nt][0], s1 = s[nt][1], s2 = s[nt][2], s3 = s[nt][3];
            int c = nt * 8 + 2 * qq;
            if (c     > rowA)     s0 = -1e30f;
            if (c + 1 > rowA)     s1 = -1e30f;
            if (c     > rowA + 8) s2 = -1e30f;
            if (c + 1 > rowA + 8) s3 = -1e30f;
            p[nt][0] = ex2x2(pack2(s0, s1));
            p[nt][1] = ex2x2(pack2(s2, s3));
        }

        #pragma unroll
        for (int kk = 0; kk < 4; ++kk) {
            if (kk > warp) break;          // P exactly 0 there
            uint32_t a0 = p[2 * kk][0];
            uint32_t a1 = p[2 * kk][1];
            uint32_t a2 = p[2 * kk + 1][0];
            uint32_t a3 = p[2 * kk + 1][1];
            mma16816(lsum, a0, a1, a2, a3, bone, bone);
            const uint32_t vrow = vb + (uint32_t)(kk * 16 + (lane & 15)) * 256;
            const uint32_t vch  = (uint32_t)(lane >> 4);
            #pragma unroll
            for (int ntp = 0; ntp < 8; ++ntp) {
                uint32_t b0, b1, b2, b3;
                ldmx4t(b0, b1, b2, b3, vrow + (((vch + 2 * ntp) ^ lx) << 4));
                mma16816(o[2 * ntp],     a0, a1, a2, a3, b0, b1);
                mma16816(o[2 * ntp + 1], a0, a1, a2, a3, b2, b3);
            }
        }
    }

    // ─── epilogue: broadcast row sums from quad leader, normalize, store ───
    const int src = lane & ~3;
    const float inv0 = 1.f / __shfl_sync(0xffffffffu, lsum[0], src);
    const float inv1 = 1.f / __shfl_sync(0xffffffffu, lsum[2], src);

    float* gO0 = outg + ((size_t)(b * Ss + q0 + rowA) * NH + h) * HS;
    float* gO1 = gO0 + (size_t)8 * NH * HS;
    #pragma unroll
    for (int nt = 0; nt < 16; ++nt) {
        int c = nt * 8 + 2 * qq;
        *(float2*)(gO0 + c) = make_float2(o[nt][0] * inv0, o[nt][1] * inv0);
        *(float2*)(gO1 + c) = make_float2(o[nt][2] * inv1, o[nt][3] * inv1);
    }
}

extern "C" void kernel_launch(void* const* d_in, const int* in_sizes, int n_in,
                              void* d_out, int out_size)
{
    (void)in_sizes; (void)n_in; (void)out_size;
    const float* q = (const float*)d_in[0];
    const float* k = (const float*)d_in[1];
    const float* v = (const float*)d_in[2];
    float* o = (float*)d_out;

    // 1) fp32 K/V -> pre-swizzled fp16 tile images (coalesced both ways)
    dim3 pgrid(NT, KVH, Bb);   // (32, 8, 2)
    pack_kv<<<pgrid, 256>>>(k, v);

    // 2) flash attention: proven __syncthreads pipeline, diag split out
    cudaFuncSetAttribute(gqa_flash_f16h,
                         cudaFuncAttributeMaxDynamicSharedMemorySize, SMEM_BYTES);
    dim3 grid(Ss / BR, NH, Bb);   // (32, 32, 2) — inverted x -> heavy first
    gqa_flash_f16h<<<grid, 128, SMEM_BYTES>>>(q, o);
}